// round 17
// baseline (speedup 1.0000x reference)
#include <cuda_runtime.h>
#include <cstdint>

#define PRIME_U      2147483647ULL
#define N_DIGITS     16
#define N_ARY        32
#define EMB          64
#define NUM_EMB      100000
#define NUM_BUCKETS  65536
#define BATCH        4096
#define PAIRS        (BATCH * N_DIGITS)   // 65536
#define N_TUPLES     (2 * PAIRS)          // 131072
#define OUT_ELEMS    (PAIRS * N_ARY)      // 2097152

struct __align__(16) PairRec {
    float w0, w1;
    int   b0, b1;
};
__device__ PairRec  g_rec[PAIRS];          // 1 MB
__device__ unsigned g_hist[NUM_BUCKETS];   // 256 KB
__device__ unsigned g_off[NUM_BUCKETS];    // 256 KB (read-only after scan)
__device__ unsigned g_cursor[NUM_BUCKETS]; // 256 KB (mutated by scatter)
__device__ unsigned g_tuple[N_TUPLES];     // 512 KB: pair | (h<<16)

struct HashConsts {
    long long seq_a[N_DIGITS];
    long long ha[2];
    long long hb[2];
};

// ---------------------------------------------------------------------------
// Host MT19937 == np.random.RandomState(42).randint, int64 dtype, range < 2^32:
// numpy's 32-bit masked-rejection branch (one next32() per attempt).
// ---------------------------------------------------------------------------
namespace host_rng {
struct MT19937 {
    uint32_t mt[624];
    int idx;
    void seed(uint32_t s) {
        for (int i = 0; i < 624; i++) {
            mt[i] = s;
            s = 1812433253u * (s ^ (s >> 30)) + (uint32_t)(i + 1);
        }
        idx = 624;
    }
    uint32_t next32() {
        if (idx >= 624) {
            for (int i = 0; i < 624; i++) {
                uint32_t y = (mt[i] & 0x80000000u) | (mt[(i + 1) % 624] & 0x7fffffffu);
                uint32_t v = mt[(i + 397) % 624] ^ (y >> 1);
                if (y & 1u) v ^= 2567483615u;
                mt[i] = v;
            }
            idx = 0;
        }
        uint32_t y = mt[idx++];
        y ^= y >> 11;
        y ^= (y << 7)  & 2636928640u;
        y ^= (y << 15) & 4022730752u;
        y ^= y >> 18;
        return y;
    }
    long long randint(long long low, long long high_excl) {
        uint32_t rng = (uint32_t)(high_excl - 1 - low);
        uint32_t mask = rng;
        mask |= mask >> 1;  mask |= mask >> 2;  mask |= mask >> 4;
        mask |= mask >> 8;  mask |= mask >> 16;
        uint32_t val;
        do { val = next32() & mask; } while (val > rng);
        return low + (long long)val;
    }
};
} // namespace host_rng

static HashConsts make_consts() {
    host_rng::MT19937 rng;
    rng.seed(42u);
    HashConsts c;
    for (int i = 0; i < N_DIGITS; i++) c.seq_a[i] = rng.randint(1, (long long)PRIME_U);
    for (int i = 0; i < 2; i++)        c.ha[i]    = rng.randint(1, (long long)PRIME_U);
    for (int i = 0; i < 2; i++)        c.hb[i]    = rng.randint(0, (long long)PRIME_U);
    return c;
}

// Mersenne reduction: x mod (2^31-1), x < 2^63.
__device__ __forceinline__ unsigned long long mod31(unsigned long long x) {
    x = (x >> 31) + (x & PRIME_U);
    x = (x >> 31) + (x & PRIME_U);
    if (x >= PRIME_U) x -= PRIME_U;
    if (x >= PRIME_U) x -= PRIME_U;
    return x;
}

// ---------------------------------------------------------------------------
// Kernel Z: zero histogram and output (out is poisoned by harness).
// ---------------------------------------------------------------------------
__global__ void zero_kernel(float* __restrict__ out) {
    int i = blockIdx.x * blockDim.x + threadIdx.x;
    int stride = gridDim.x * blockDim.x;
    for (int k = i; k < OUT_ELEMS; k += stride) out[k] = 0.0f;
    for (int k = i; k < NUM_BUCKETS; k += stride) g_hist[k] = 0u;
}

// ---------------------------------------------------------------------------
// Kernel 1: detection (block-local ballot) + prefix hashes -> g_rec + histogram.
// Raw cumsum has no mod on the dependency chain (terms < 2^36, sum < 2^40).
// ---------------------------------------------------------------------------
__global__ void hash_kernel(const void* __restrict__ seq_raw,
                            const float* __restrict__ iw,
                            HashConsts c) {
    int b = blockIdx.x * blockDim.x + threadIdx.x;   // 32 blocks * 128
    const int*   s32 = (const int*)seq_raw;
    const float* f32 = (const float*)seq_raw;

    // --- layout detection over this block's 128 rows (first 16 raw words each)
    __shared__ unsigned s_odd, s_big;
    if (threadIdx.x == 0) { s_odd = 0u; s_big = 0u; }
    __syncthreads();
    {
        const unsigned* u32 = (const unsigned*)seq_raw;
        unsigned odd = 0u, big = 0u;
#pragma unroll
        for (int j = 0; j < N_DIGITS; j++) {
            int i = b * N_DIGITS + j;
            unsigned v = u32[i];
            if ((i & 1) && v != 0u) odd = 1u;
            if (v >= 0x3F000000u)   big = 1u;
        }
        if (__ballot_sync(0xffffffffu, odd) && (threadIdx.x & 31) == 0) atomicOr(&s_odd, 1u);
        if (__ballot_sync(0xffffffffu, big) && (threadIdx.x & 31) == 0) atomicOr(&s_big, 1u);
    }
    __syncthreads();
    int mode = s_big ? 2 : (s_odd ? 0 : 1);   // 0=int32, 1=int64 LE, 2=float32

    unsigned long long raw[N_DIGITS];
    unsigned long long acc = 0;
    int len = 0;
#pragma unroll
    for (int d = 0; d < N_DIGITS; d++) {
        int idx = b * N_DIGITS + d;
        long long v;
        if (mode == 0)      v = (long long)s32[idx];
        else if (mode == 1) v = (long long)s32[2 * idx];
        else                v = (long long)f32[idx];
        if (v != 0) len++;
        acc += (unsigned long long)c.seq_a[d] * (unsigned long long)v;
        raw[d] = acc;
    }
    int last = (len - 1 > 0) ? (len - 1) : 0;

#pragma unroll
    for (int d = 0; d < N_DIGITS; d++) {
        unsigned long long id = mod31(raw[d < last ? d : last]);
        int iwrow = (int)(id % NUM_EMB);
        PairRec r;
        r.w0 = iw[(size_t)iwrow * 2 + 0];
        r.w1 = iw[(size_t)iwrow * 2 + 1];
        r.b0 = (int)(mod31((unsigned long long)c.ha[0] * id + (unsigned long long)c.hb[0]) & (NUM_BUCKETS - 1));
        r.b1 = (int)(mod31((unsigned long long)c.ha[1] * id + (unsigned long long)c.hb[1]) & (NUM_BUCKETS - 1));
        g_rec[d * BATCH + b] = r;
        atomicAdd(&g_hist[r.b0], 1u);
        atomicAdd(&g_hist[r.b1], 1u);
    }
}

// ---------------------------------------------------------------------------
// Kernel 2: exclusive scan of the 65536-entry histogram (1 block, 1024 thr,
// 64 entries per thread; two passes over hist to avoid register spills).
// ---------------------------------------------------------------------------
__global__ void scan_kernel() {
    __shared__ unsigned ssum[1024];
    int t = threadIdx.x;
    unsigned sum = 0;
    for (int j = 0; j < 64; j++) sum += g_hist[t * 64 + j];
    ssum[t] = sum;
    __syncthreads();
    for (int off = 1; off < 1024; off <<= 1) {
        unsigned v = (t >= off) ? ssum[t - off] : 0u;
        __syncthreads();
        ssum[t] += v;
        __syncthreads();
    }
    unsigned run = (t == 0) ? 0u : ssum[t - 1];
    for (int j = 0; j < 64; j++) {
        unsigned h = g_hist[t * 64 + j];
        g_off[t * 64 + j]    = run;
        g_cursor[t * 64 + j] = run;
        run += h;
    }
}

// ---------------------------------------------------------------------------
// Kernel 3: scatter tuples (pair, hash) into bucket segments.
// ---------------------------------------------------------------------------
__global__ void scatter_kernel() {
    int p = blockIdx.x * blockDim.x + threadIdx.x;
    if (p >= PAIRS) return;
    PairRec r = g_rec[p];
    unsigned pos0 = atomicAdd(&g_cursor[r.b0], 1u);
    g_tuple[pos0] = (unsigned)p;              // h = 0
    unsigned pos1 = atomicAdd(&g_cursor[r.b1], 1u);
    g_tuple[pos1] = (unsigned)p | 0x10000u;   // h = 1
}

// ---------------------------------------------------------------------------
// Kernel 4: one block per bucket. Hoist the 8KB row into registers (4 float4
// per thread), then loop tuples: out[p,a] += w_h * dot(row[a], rep[p]).
// Exactly two float atomicAdds per output element (commutative -> exact).
// ---------------------------------------------------------------------------
__global__ void __launch_bounds__(128)
compute_kernel(const float* __restrict__ rep,
               const float* __restrict__ table,
               float* __restrict__ out) {
    int B = blockIdx.x;
    unsigned n = g_hist[B];
    if (n == 0) return;
    unsigned start = g_off[B];

    int tid  = threadIdx.x;
    int warp = tid >> 5;
    int lane = tid & 31;
    int half = lane >> 4;
    int hl   = lane & 15;

    const float4* row = (const float4*)(table + (size_t)B * (N_ARY * EMB));
    float4 rv[4];
#pragma unroll
    for (int i = 0; i < 4; i++) {
        int a = warp * 8 + 2 * i + half;
        rv[i] = __ldg(&row[a * 16 + hl]);
    }

    for (unsigned t = 0; t < n; t++) {
        unsigned pay = g_tuple[start + t];
        int p = (int)(pay & 0xFFFFu);
        int h = (int)(pay >> 16);
        PairRec rec = g_rec[p];
        float w = h ? rec.w1 : rec.w0;
        int d = p >> 12;
        int b = p & (BATCH - 1);
        size_t bd = (size_t)b * N_DIGITS + d;
        float4 r = __ldg(&((const float4*)(rep + bd * EMB))[hl]);
        float* o = out + bd * N_ARY;
#pragma unroll
        for (int i = 0; i < 4; i++) {
            float partial = rv[i].x * r.x + rv[i].y * r.y + rv[i].z * r.z + rv[i].w * r.w;
#pragma unroll
            for (int off = 8; off > 0; off >>= 1)
                partial += __shfl_xor_sync(0xffffffffu, partial, off);
            if (hl == 0)
                atomicAdd(&o[warp * 8 + 2 * i + half], w * partial);
        }
    }
}

// ---------------------------------------------------------------------------
// Launch. Inputs identified BY SIZE (robust to ordering):
//   seq: smallest, table: largest, iw: 200000, rep: 4194304.
// ---------------------------------------------------------------------------
extern "C" void kernel_launch(void* const* d_in, const int* in_sizes, int n_in,
                              void* d_out, int out_size) {
    (void)out_size;
    const void*  seq   = nullptr;
    const float* rep   = nullptr;
    const float* iw    = nullptr;
    const float* table = nullptr;

    long long best_small = 0x7fffffffffffffffLL, best_big = -1;
    int small_i = 0, big_i = 0;
    for (int i = 0; i < n_in; i++) {
        long long sz = in_sizes[i];
        if (sz < best_small) { best_small = sz; seq = d_in[i]; small_i = i; }
        if (sz > best_big)   { best_big = sz; table = (const float*)d_in[i]; big_i = i; }
    }
    for (int i = 0; i < n_in; i++) {
        if (i == small_i || i == big_i) continue;
        if ((long long)in_sizes[i] < 1000000) iw = (const float*)d_in[i];
        else                                  rep = (const float*)d_in[i];
    }

    HashConsts c = make_consts();   // host-only; baked into graph node params

    zero_kernel<<<256, 1024>>>((float*)d_out);
    hash_kernel<<<BATCH / 128, 128>>>(seq, iw, c);
    scan_kernel<<<1, 1024>>>();
    scatter_kernel<<<PAIRS / 128, 128>>>();
    compute_kernel<<<NUM_BUCKETS, 128>>>(rep, table, (float*)d_out);
}